// round 2
// baseline (speedup 1.0000x reference)
#include <cuda_runtime.h>
#include <math.h>

#define NK 1024
#define H  128
#define HH 64
#define TI 16
#define TJ 16

// Scratch (allocation-free requirement: __device__ globals)
__device__ float g_pi[NK * H];
__device__ float g_pj[NK * H];
__device__ float g_adj[NK * NK];

__device__ __forceinline__ float gelu_exact(float x) {
    // jax.nn.gelu(approximate=False): 0.5*x*(1+erf(x/sqrt(2)))
    return 0.5f * x * (1.0f + erff(x * 0.7071067811865476f));
}

// ---------------------------------------------------------------------------
// prep: pi = z @ eW1[:H], pj = z @ eW1[H:], coords = coord_mlp(z)
// grid = NK blocks, 128 threads
// ---------------------------------------------------------------------------
__global__ __launch_bounds__(128)
void prep_kernel(const float* __restrict__ z,
                 const float* __restrict__ cW1, const float* __restrict__ cb1,
                 const float* __restrict__ cW2, const float* __restrict__ cb2,
                 const float* __restrict__ eW1,
                 float* __restrict__ out_coords)
{
    const int i = blockIdx.x;
    const int t = threadIdx.x;   // 0..127
    __shared__ float zs[H];
    __shared__ float c1s[HH];

    zs[t] = z[i * H + t];
    __syncthreads();

    float accA = 0.f, accB = 0.f;
    #pragma unroll 8
    for (int k = 0; k < H; k++) {
        const float zk = zs[k];
        accA = fmaf(zk, eW1[k * H + t],       accA);
        accB = fmaf(zk, eW1[(H + k) * H + t], accB);
    }
    g_pi[i * H + t] = accA;
    g_pj[i * H + t] = accB;

    if (t < HH) {
        float acc = cb1[t];
        #pragma unroll 8
        for (int k = 0; k < H; k++) acc = fmaf(zs[k], cW1[k * HH + t], acc);
        c1s[t] = gelu_exact(acc);
    }
    __syncthreads();

    if (t < 2) {
        float acc = cb2[t];
        #pragma unroll 8
        for (int n = 0; n < HH; n++) acc = fmaf(c1s[n], cW2[n * 2 + t], acc);
        out_coords[i * 2 + t] = acc;
    }
}

// ---------------------------------------------------------------------------
// edge: adj_raw[i][j] = edge_mlp tail on gelu(pi[i]+pj[j]+eb1)
// grid = (NK/TJ, NK/TI), 256 threads, one (i,j) pair per thread
// ---------------------------------------------------------------------------
__global__ __launch_bounds__(256)
void edge_kernel(const float* __restrict__ eb1, const float* __restrict__ eW2,
                 const float* __restrict__ eb2, const float* __restrict__ eW3,
                 const float* __restrict__ eb3)
{
    __shared__ float pjs[TJ][H + 4];   // +4 pad: kill stride-128 bank conflicts
    __shared__ float W2s[H * HH];      // 32 KB, broadcast reads
    __shared__ float b2s[HH];
    __shared__ float W3s[HH];
    __shared__ float b3s;

    const int t  = threadIdx.x;
    const int i0 = blockIdx.y * TI;
    const int j0 = blockIdx.x * TJ;

    // pj tile with eb1 pre-added (fuses bias into the tile load)
    for (int idx = t; idx < TJ * H; idx += 256) {
        const int r = idx >> 7;         // idx / 128
        const int c = idx & (H - 1);    // idx % 128
        pjs[r][c] = g_pj[(j0 + r) * H + c] + eb1[c];
    }
    for (int idx = t; idx < H * HH; idx += 256) W2s[idx] = eW2[idx];
    if (t < HH) { b2s[t] = eb2[t]; W3s[t] = eW3[t]; }
    if (t == 0) b3s = eb3[0];
    __syncthreads();

    const int il = t >> 4;        // 0..15
    const int jl = t & (TJ - 1);  // 0..15

    float acc[HH];
    #pragma unroll
    for (int n = 0; n < HH; n++) acc[n] = 0.f;

    const float4* pi4 = reinterpret_cast<const float4*>(&g_pi[(i0 + il) * H]);
    const float4* pj4 = reinterpret_cast<const float4*>(&pjs[jl][0]); // 528B rows, 16B aligned

    #pragma unroll 2
    for (int h4 = 0; h4 < H / 4; h4++) {
        const float4 a = __ldg(&pi4[h4]);   // 16-lane broadcast, L2-resident
        const float4 b = pj4[h4];
        float v[4];
        v[0] = gelu_exact(a.x + b.x);
        v[1] = gelu_exact(a.y + b.y);
        v[2] = gelu_exact(a.z + b.z);
        v[3] = gelu_exact(a.w + b.w);
        #pragma unroll
        for (int hh = 0; hh < 4; hh++) {
            const float4* w4 = reinterpret_cast<const float4*>(&W2s[(h4 * 4 + hh) * HH]);
            const float vh = v[hh];
            #pragma unroll
            for (int n4 = 0; n4 < HH / 4; n4++) {
                const float4 w = w4[n4];
                acc[n4 * 4 + 0] = fmaf(vh, w.x, acc[n4 * 4 + 0]);
                acc[n4 * 4 + 1] = fmaf(vh, w.y, acc[n4 * 4 + 1]);
                acc[n4 * 4 + 2] = fmaf(vh, w.z, acc[n4 * 4 + 2]);
                acc[n4 * 4 + 3] = fmaf(vh, w.w, acc[n4 * 4 + 3]);
            }
        }
    }

    float s = b3s;
    #pragma unroll
    for (int n = 0; n < HH; n++)
        s = fmaf(gelu_exact(acc[n] + b2s[n]), W3s[n], s);

    g_adj[(i0 + il) * NK + (j0 + jl)] = s;
}

// ---------------------------------------------------------------------------
// symmetrize: out = (adj + adj^T) / 2   (adj is L2-resident, 4 MB)
// ---------------------------------------------------------------------------
__global__ __launch_bounds__(256)
void sym_kernel(float* __restrict__ out_adj)
{
    const int idx = blockIdx.x * 256 + threadIdx.x;
    const int i = idx >> 10;
    const int j = idx & (NK - 1);
    out_adj[idx] = 0.5f * (g_adj[idx] + g_adj[j * NK + i]);
}

// ---------------------------------------------------------------------------
extern "C" void kernel_launch(void* const* d_in, const int* in_sizes, int n_in,
                              void* d_out, int out_size)
{
    const float* z   = (const float*)d_in[0];
    const float* cW1 = (const float*)d_in[1];
    const float* cb1 = (const float*)d_in[2];
    const float* cW2 = (const float*)d_in[3];
    const float* cb2 = (const float*)d_in[4];
    const float* eW1 = (const float*)d_in[5];
    const float* eb1 = (const float*)d_in[6];
    const float* eW2 = (const float*)d_in[7];
    const float* eb2 = (const float*)d_in[8];
    const float* eW3 = (const float*)d_in[9];
    const float* eb3 = (const float*)d_in[10];
    float* out = (float*)d_out;

    // out layout: coords_pred [1024,2] then adj_logits [1024,1024]
    prep_kernel<<<NK, 128>>>(z, cW1, cb1, cW2, cb2, eW1, out);
    edge_kernel<<<dim3(NK / TJ, NK / TI), TI * TJ>>>(eb1, eW2, eb2, eW3, eb3);
    sym_kernel<<<(NK * NK) / 256, 256>>>(out + NK * 2);
}

// round 3
// speedup vs baseline: 1.0013x; 1.0013x over previous
#include <cuda_runtime.h>
#include <math.h>

#define NK 1024
#define H  128
#define HH 64
#define TI 16
#define TJ 16

// Scratch (allocation-free requirement: __device__ globals)
__device__ float g_pi[NK * H];
__device__ float g_pj[NK * H];
__device__ float g_adj[NK * NK];

__device__ __forceinline__ float gelu_exact(float x) {
    // jax.nn.gelu(approximate=False): 0.5*x*(1+erf(x/sqrt(2)))
    return 0.5f * x * (1.0f + erff(x * 0.7071067811865476f));
}

// ---------------------------------------------------------------------------
// prep: pi = z @ eW1[:H], pj = z @ eW1[H:], coords = coord_mlp(z)
// grid = NK blocks, 128 threads
// ---------------------------------------------------------------------------
__global__ __launch_bounds__(128)
void prep_kernel(const float* __restrict__ z,
                 const float* __restrict__ cW1, const float* __restrict__ cb1,
                 const float* __restrict__ cW2, const float* __restrict__ cb2,
                 const float* __restrict__ eW1,
                 float* __restrict__ out_coords)
{
    const int i = blockIdx.x;
    const int t = threadIdx.x;   // 0..127
    __shared__ float zs[H];
    __shared__ float c1s[HH];

    zs[t] = z[i * H + t];
    __syncthreads();

    float accA = 0.f, accB = 0.f;
    #pragma unroll 8
    for (int k = 0; k < H; k++) {
        const float zk = zs[k];
        accA = fmaf(zk, eW1[k * H + t],       accA);
        accB = fmaf(zk, eW1[(H + k) * H + t], accB);
    }
    g_pi[i * H + t] = accA;
    g_pj[i * H + t] = accB;

    if (t < HH) {
        float acc = cb1[t];
        #pragma unroll 8
        for (int k = 0; k < H; k++) acc = fmaf(zs[k], cW1[k * HH + t], acc);
        c1s[t] = gelu_exact(acc);
    }
    __syncthreads();

    if (t < 2) {
        float acc = cb2[t];
        #pragma unroll 8
        for (int n = 0; n < HH; n++) acc = fmaf(c1s[n], cW2[n * 2 + t], acc);
        out_coords[i * 2 + t] = acc;
    }
}

// ---------------------------------------------------------------------------
// edge: adj_raw[i][j] = edge_mlp tail on gelu(pi[i]+pj[j]+eb1)
// grid = (NK/TJ, NK/TI), 256 threads, one (i,j) pair per thread
// ---------------------------------------------------------------------------
__global__ __launch_bounds__(256)
void edge_kernel(const float* __restrict__ eb1, const float* __restrict__ eW2,
                 const float* __restrict__ eb2, const float* __restrict__ eW3,
                 const float* __restrict__ eb3)
{
    __shared__ float pjs[TJ][H + 4];   // +4 pad: kill stride-128 bank conflicts
    __shared__ float W2s[H * HH];      // 32 KB, broadcast reads
    __shared__ float b2s[HH];
    __shared__ float W3s[HH];
    __shared__ float b3s;

    const int t  = threadIdx.x;
    const int i0 = blockIdx.y * TI;
    const int j0 = blockIdx.x * TJ;

    // pj tile with eb1 pre-added (fuses bias into the tile load)
    for (int idx = t; idx < TJ * H; idx += 256) {
        const int r = idx >> 7;         // idx / 128
        const int c = idx & (H - 1);    // idx % 128
        pjs[r][c] = g_pj[(j0 + r) * H + c] + eb1[c];
    }
    for (int idx = t; idx < H * HH; idx += 256) W2s[idx] = eW2[idx];
    if (t < HH) { b2s[t] = eb2[t]; W3s[t] = eW3[t]; }
    if (t == 0) b3s = eb3[0];
    __syncthreads();

    const int il = t >> 4;        // 0..15
    const int jl = t & (TJ - 1);  // 0..15

    float acc[HH];
    #pragma unroll
    for (int n = 0; n < HH; n++) acc[n] = 0.f;

    const float4* pi4 = reinterpret_cast<const float4*>(&g_pi[(i0 + il) * H]);
    const float4* pj4 = reinterpret_cast<const float4*>(&pjs[jl][0]); // 528B rows, 16B aligned

    #pragma unroll 2
    for (int h4 = 0; h4 < H / 4; h4++) {
        const float4 a = __ldg(&pi4[h4]);   // 16-lane broadcast, L2-resident
        const float4 b = pj4[h4];
        float v[4];
        v[0] = gelu_exact(a.x + b.x);
        v[1] = gelu_exact(a.y + b.y);
        v[2] = gelu_exact(a.z + b.z);
        v[3] = gelu_exact(a.w + b.w);
        #pragma unroll
        for (int hh = 0; hh < 4; hh++) {
            const float4* w4 = reinterpret_cast<const float4*>(&W2s[(h4 * 4 + hh) * HH]);
            const float vh = v[hh];
            #pragma unroll
            for (int n4 = 0; n4 < HH / 4; n4++) {
                const float4 w = w4[n4];
                acc[n4 * 4 + 0] = fmaf(vh, w.x, acc[n4 * 4 + 0]);
                acc[n4 * 4 + 1] = fmaf(vh, w.y, acc[n4 * 4 + 1]);
                acc[n4 * 4 + 2] = fmaf(vh, w.z, acc[n4 * 4 + 2]);
                acc[n4 * 4 + 3] = fmaf(vh, w.w, acc[n4 * 4 + 3]);
            }
        }
    }

    float s = b3s;
    #pragma unroll
    for (int n = 0; n < HH; n++)
        s = fmaf(gelu_exact(acc[n] + b2s[n]), W3s[n], s);

    g_adj[(i0 + il) * NK + (j0 + jl)] = s;
}

// ---------------------------------------------------------------------------
// symmetrize: out = (adj + adj^T) / 2   (adj is L2-resident, 4 MB)
// ---------------------------------------------------------------------------
__global__ __launch_bounds__(256)
void sym_kernel(float* __restrict__ out_adj)
{
    const int idx = blockIdx.x * 256 + threadIdx.x;
    const int i = idx >> 10;
    const int j = idx & (NK - 1);
    out_adj[idx] = 0.5f * (g_adj[idx] + g_adj[j * NK + i]);
}

// ---------------------------------------------------------------------------
extern "C" void kernel_launch(void* const* d_in, const int* in_sizes, int n_in,
                              void* d_out, int out_size)
{
    const float* z   = (const float*)d_in[0];
    const float* cW1 = (const float*)d_in[1];
    const float* cb1 = (const float*)d_in[2];
    const float* cW2 = (const float*)d_in[3];
    const float* cb2 = (const float*)d_in[4];
    const float* eW1 = (const float*)d_in[5];
    const float* eb1 = (const float*)d_in[6];
    const float* eW2 = (const float*)d_in[7];
    const float* eb2 = (const float*)d_in[8];
    const float* eW3 = (const float*)d_in[9];
    const float* eb3 = (const float*)d_in[10];
    float* out = (float*)d_out;

    // out layout: coords_pred [1024,2] then adj_logits [1024,1024]
    prep_kernel<<<NK, 128>>>(z, cW1, cb1, cW2, cb2, eW1, out);
    edge_kernel<<<dim3(NK / TJ, NK / TI), TI * TJ>>>(eb1, eW2, eb2, eW3, eb3);
    sym_kernel<<<(NK * NK) / 256, 256>>>(out + NK * 2);
}